// round 17
// baseline (speedup 1.0000x reference)
#include <cuda_runtime.h>
#include <math.h>

// Shape-specialized: H=1024, N_HALF=32, L=4096, CHANNELS=1
// Grid = 1024 (one block per h), TPB=128, 7 blocks/SM -> FULL grid residency.
// Fully table-driven main loop: ZERO MUFU, no dependent V-spine.
//   l = t + 128*j,  t = tl + 32*tw,  j = 8*jt + r
//   K[h,l] = sum_n Re( (2Ceff*dA^tl) * dA^{32tw+1024jt} * dA^{128r} )
//   V[jt]  = u0[n][tl] * rot[n][tw][jt]        (4 indep complex mults)
//   acc[..]= fma2(V, {c_r dup}, fma2(V', {d_r dup}, acc))
#define HH    1024
#define NH    32
#define TPB   128
#define LL    4096

typedef unsigned long long u64;

__device__ __forceinline__ u64 pk2(float lo, float hi) {
    u64 r; asm("mov.b64 %0, {%1,%2};" : "=l"(r) : "f"(lo), "f"(hi)); return r;
}
__device__ __forceinline__ void upk2(float& lo, float& hi, u64 v) {
    asm("mov.b64 {%0,%1}, %2;" : "=f"(lo), "=f"(hi) : "l"(v));
}
__device__ __forceinline__ u64 fma2(u64 a, u64 b, u64 c) {
    u64 r; asm("fma.rn.f32x2 %0, %1, %2, %3;" : "=l"(r) : "l"(a), "l"(b), "l"(c)); return r;
}
__device__ __forceinline__ u64 add2(u64 a, u64 b) {
    u64 r; asm("add.rn.f32x2 %0, %1, %2;" : "=l"(r) : "l"(a), "l"(b)); return r;
}

__global__ void __launch_bounds__(TPB, 7)
sskernel_diag(const float* __restrict__ log_dt,
              const float* __restrict__ B_ri,
              const float* __restrict__ C_ri,
              const float* __restrict__ inv_A_real,
              const float* __restrict__ A_imag,
              float* __restrict__ out)
{
    __shared__ float4 s_par[NH];             // {2Cr, 2Ci, lg, th}
    __shared__ float2 s_u0[NH][32];          // 2Ceff * dA^tl          (8 KB)
    __shared__ float4 s_rotA[NH][4];         // (n,tw): {jt0.r,jt0.i,jt1.r,jt1.i} (2 KB)
    __shared__ float4 s_rotB[NH][4];         // (n,tw): {jt2.r,jt2.i,jt3.r,jt3.i} (2 KB)
    __shared__ ulonglong2 s_tab[NH][8];      // [r=1..7]: {c,c,d,d}, c=Re dA^128r, d=-Im (4 KB)

    const int h = blockIdx.x;
    const int t = threadIdx.x;

    // ---- phase 1: per-(h,n) base params, fp32 (threads 0..31) ----
    if (t < NH) {
        const int n  = t;
        const int hn = h * NH + n;
        float dt = expf(log_dt[h]);
        float Ar = -expf(inv_A_real[hn]);
        float Ai = A_imag[hn];
        float zr = Ar * dt, zi = Ai * dt;                  // dtA
        float dr = 1.0f - 0.5f * zr, di = -0.5f * zi;      // 1 - dtA/2
        float inv = 1.0f / (dr * dr + di * di);
        float idr =  dr * inv, idi = -di * inv;            // 1/(1-dtA/2)
        float nr = 1.0f + 0.5f * zr, ni = 0.5f * zi;       // 1 + dtA/2
        float dAr = nr * idr - ni * idi;                   // bilinear dA
        float dAi = nr * idi + ni * idr;
        float Br = B_ri[2 * hn],  Bi = B_ri[2 * hn + 1];
        float Cr = C_ri[2 * hn],  Ci = C_ri[2 * hn + 1];
        float bcr = Br * Cr - Bi * Ci, bci = Br * Ci + Bi * Cr;
        float4 par;
        par.x = 2.0f * (bcr * idr - bci * idi) * dt;       // 2*Ceff_r
        par.y = 2.0f * (bcr * idi + bci * idr) * dt;       // 2*Ceff_i
        par.z = 0.5f * logf(dAr * dAr + dAi * dAi);        // lg = log|dA|
        par.w = atan2f(dAi, dAr);                          // th = arg(dA)
        s_par[n] = par;
    }
    __syncthreads();

    // ---- phase 2: all tables via MUFU (one-time, all 128 threads) ----
    // u0[n][tl] = 2Ceff * dA^tl : 1024 entries, 8 per thread
    #pragma unroll
    for (int k = 0; k < 8; k++) {
        const int e  = t + TPB * k;          // 0..1023
        const int n  = e >> 5, tl_ = e & 31;
        const float4 P = s_par[n];
        const float f = (float)tl_;
        float m = __expf(f * P.z);
        float sn, cs; __sincosf(f * P.w, &sn, &cs);
        s_u0[n][tl_] = make_float2(m * (P.x * cs - P.y * sn),
                                   m * (P.y * cs + P.x * sn));
    }
    // rot[n][tw][jt] = dA^(32*tw + 1024*jt) : 512 entries, 4 per thread
    #pragma unroll
    for (int k = 0; k < 4; k++) {
        const int e   = t + TPB * k;         // 0..511
        const int n   = e >> 4;
        const int rem = e & 15, tw_ = rem >> 2, jt = rem & 3;
        const float4 P = s_par[n];
        const float f = (float)(32 * tw_ + 1024 * jt);
        float m = __expf(f * P.z);
        float sn, cs; __sincosf(f * P.w, &sn, &cs);
        float* dst = (jt < 2) ? (float*)&s_rotA[n][tw_] : (float*)&s_rotB[n][tw_];
        dst[(jt & 1) * 2]     = m * cs;
        dst[(jt & 1) * 2 + 1] = m * sn;
    }
    // coeff table: dA^{128r}, r=1..7, duplicated lanes: 224 entries
    #pragma unroll
    for (int k = 0; k < 2; k++) {
        const int e = t + TPB * k;           // 0..255
        const int n = e >> 3, r = e & 7;
        if (r > 0) {
            const float4 P = s_par[n];
            const float f = 128.0f * (float)r;
            float m = __expf(f * P.z);
            float sn, cs; __sincosf(f * P.w, &sn, &cs);
            const float a = m * cs, b = -m * sn;
            float* tf = (float*)&s_tab[n][r];
            tf[0] = a; tf[1] = a; tf[2] = b; tf[3] = b;
        }
    }
    __syncthreads();

    // ---- main: pure LDS + FMA, no MUFU, no cross-n dependencies ----
    u64 acc[16];                 // acc[r]=(jt0,jt1); acc[8+r]=(jt2,jt3)
    #pragma unroll
    for (int j = 0; j < 16; j++) acc[j] = 0ull;

    const int tl = t & 31, tw = t >> 5;

    #pragma unroll 2
    for (int n = 0; n < NH; n++) {
        const float2 u  = s_u0[n][tl];       // LDS.64 (conflict-free)
        const float4 rA = s_rotA[n][tw];     // LDS.128 broadcast
        const float4 rB = s_rotB[n][tw];     // LDS.128 broadcast
        // V[jt] = u * rot[jt] — 4 independent complex mults
        const float vr0 = u.x * rA.x - u.y * rA.y, vi0 = u.x * rA.y + u.y * rA.x;
        const float vr1 = u.x * rA.z - u.y * rA.w, vi1 = u.x * rA.w + u.y * rA.z;
        const float vr2 = u.x * rB.x - u.y * rB.y, vi2 = u.x * rB.y + u.y * rB.x;
        const float vr3 = u.x * rB.z - u.y * rB.w, vi3 = u.x * rB.w + u.y * rB.z;
        const u64 Vr01 = pk2(vr0, vr1), Vi01 = pk2(vi0, vi1);
        const u64 Vr23 = pk2(vr2, vr3), Vi23 = pk2(vi2, vi3);

        acc[0] = add2(acc[0], Vr01);
        acc[8] = add2(acc[8], Vr23);
        #pragma unroll
        for (int r = 1; r < 8; r++) {
            const ulonglong2 q = s_tab[n][r];    // {c dup, d dup}: 1 LDS.128
            acc[r]     = fma2(Vr01, q.x, fma2(Vi01, q.y, acc[r]));
            acc[8 + r] = fma2(Vr23, q.x, fma2(Vi23, q.y, acc[8 + r]));
        }
    }

    // ---- coalesced stores (2x folded into Ceff) ----
    // acc[r]: lo -> j=r, hi -> j=8+r ; acc[8+r]: lo -> j=16+r, hi -> j=24+r
    float* o = out + (size_t)h * LL + t;
    #pragma unroll
    for (int r = 0; r < 8; r++) {
        float lo, hi;
        upk2(lo, hi, acc[r]);
        o[r * TPB]        = lo;
        o[(8 + r) * TPB]  = hi;
        upk2(lo, hi, acc[8 + r]);
        o[(16 + r) * TPB] = lo;
        o[(24 + r) * TPB] = hi;
    }
}

extern "C" void kernel_launch(void* const* d_in, const int* in_sizes, int n_in,
                              void* d_out, int out_size)
{
    const float* log_dt     = (const float*)d_in[0];   // (H,)
    const float* B_ri       = (const float*)d_in[1];   // (H, N, 2)
    const float* C_ri       = (const float*)d_in[2];   // (1, H, N, 2)
    const float* inv_A_real = (const float*)d_in[3];   // (H, N)
    const float* A_imag     = (const float*)d_in[4];   // (H, N)
    float* out = (float*)d_out;                        // (1, H, L)

    sskernel_diag<<<HH, TPB>>>(log_dt, B_ri, C_ri, inv_A_real, A_imag, out);
}